// round 8
// baseline (speedup 1.0000x reference)
#include <cuda_runtime.h>
#include <cuda_bf16.h>

// Problem dims (fixed by reference)
#define HWDIM 196
#define BATCH 64
#define DDIM  768
#define EDIM  256
#define CDIM  10
#define M1    (BATCH * HWDIM)   // 12544 rows (b,h)

typedef unsigned long long ull;

// Packed dual-fp32 FMA: acc.{lo,hi} += a.{lo,hi} * b.{lo,hi}
#define FMA2(acc, a, b) \
    asm("fma.rn.f32x2 %0, %1, %2, %0;" : "+l"(acc) : "l"(a), "l"(b))
#define PACK2(p, v) \
    asm("mov.b64 %0, {%1, %1};" : "=l"(p) : "f"(v))
#define UNPACK2(lo, hi, p) \
    asm("mov.b64 {%0, %1}, %2;" : "=f"(lo), "=f"(hi) : "l"(p))

__device__ __forceinline__ void cp16(void* smem_dst, const void* gsrc) {
    unsigned sa = (unsigned)__cvta_generic_to_shared(smem_dst);
    asm volatile("cp.async.cg.shared.global [%0], [%1], 16;" :: "r"(sa), "l"(gsrc));
}
#define CP_COMMIT() asm volatile("cp.async.commit_group;")
#define CP_WAIT0()  asm volatile("cp.async.wait_group 0;")

// Scratch (static device global — no allocation anywhere)
__device__ float g_S[(size_t)M1 * EDIM];            // sign pattern, 12.8 MB

// ---------------------------------------------------------------------------
// Kernel 1: S = (X @ ag_w^T + ag_b) > 0   (M=12544, N=256, K=768, fp32 exact)
// Tile 128(M) x 64(N), 128 threads, micro 8Mx8N via f32x2 (4 M-pairs x 8 N),
// BK=16, double-buffered smem. grid (4, 98). LDS/MAC = 0.25 (was 0.31).
// ---------------------------------------------------------------------------
__global__ __launch_bounds__(128) void k1_sign_gemm(
    const float* __restrict__ X, const float* __restrict__ W,
    const float* __restrict__ bias)
{
    __shared__ float Xs[2][16][132];
    __shared__ float Ws[2][16][72];

    const int tid = threadIdx.x;
    const int tx  = tid & 7;      // N dir: 8 cols each
    const int ty  = tid >> 3;     // M dir: 8 rows each (0..15)
    const int m0  = blockIdx.y * 128;
    const int n0  = blockIdx.x * 64;

    const int gr  = tid >> 2;          // 0..31
    const int gc4 = (tid & 3) * 4;     // k sub-offset

    float4 xa[4], wa[2];

    auto gload = [&](int k0) {
        #pragma unroll
        for (int l = 0; l < 4; l++)
            xa[l] = *reinterpret_cast<const float4*>(
                &X[(size_t)(m0 + gr + l * 32) * DDIM + k0 + gc4]);
        #pragma unroll
        for (int l = 0; l < 2; l++)
            wa[l] = *reinterpret_cast<const float4*>(
                &W[(size_t)(n0 + gr + l * 32) * DDIM + k0 + gc4]);
    };
    auto sstore = [&](int nb) {
        #pragma unroll
        for (int l = 0; l < 4; l++) {
            Xs[nb][gc4 + 0][gr + l * 32] = xa[l].x;
            Xs[nb][gc4 + 1][gr + l * 32] = xa[l].y;
            Xs[nb][gc4 + 2][gr + l * 32] = xa[l].z;
            Xs[nb][gc4 + 3][gr + l * 32] = xa[l].w;
        }
        #pragma unroll
        for (int l = 0; l < 2; l++) {
            Ws[nb][gc4 + 0][gr + l * 32] = wa[l].x;
            Ws[nb][gc4 + 1][gr + l * 32] = wa[l].y;
            Ws[nb][gc4 + 2][gr + l * 32] = wa[l].z;
            Ws[nb][gc4 + 3][gr + l * 32] = wa[l].w;
        }
    };

    gload(0);
    sstore(0);
    __syncthreads();

    ull acc2[4][8];
    #pragma unroll
    for (int i = 0; i < 4; i++)
        #pragma unroll
        for (int j = 0; j < 8; j++) acc2[i][j] = 0ull;

    int buf = 0;
    const int NT = DDIM / 16;   // 48
    for (int t = 0; t < NT; t++) {
        if (t < NT - 1) gload((t + 1) * 16);

        #pragma unroll
        for (int kk = 0; kk < 16; kk++) {
            ulonglong2 a01 = *reinterpret_cast<const ulonglong2*>(
                &Xs[buf][kk][ty * 8 + 0]);
            ulonglong2 a23 = *reinterpret_cast<const ulonglong2*>(
                &Xs[buf][kk][ty * 8 + 4]);
            ull ra2[4] = { a01.x, a01.y, a23.x, a23.y };
            float rbv[8];
            *reinterpret_cast<float4*>(&rbv[0]) =
                *reinterpret_cast<const float4*>(&Ws[buf][kk][tx * 8 + 0]);
            *reinterpret_cast<float4*>(&rbv[4]) =
                *reinterpret_cast<const float4*>(&Ws[buf][kk][tx * 8 + 4]);
            ull rb2[8];
            #pragma unroll
            for (int j = 0; j < 8; j++) PACK2(rb2[j], rbv[j]);
            #pragma unroll
            for (int i = 0; i < 4; i++)
                #pragma unroll
                for (int j = 0; j < 8; j++) FMA2(acc2[i][j], ra2[i], rb2[j]);
        }

        if (t < NT - 1) sstore(buf ^ 1);
        buf ^= 1;
        __syncthreads();
    }

    float accf[8][8];
    #pragma unroll
    for (int p = 0; p < 4; p++)
        #pragma unroll
        for (int j = 0; j < 8; j++)
            UNPACK2(accf[2 * p][j], accf[2 * p + 1][j], acc2[p][j]);

    float bv[8];
    #pragma unroll
    for (int j = 0; j < 8; j++) bv[j] = bias[n0 + tx * 8 + j];

    #pragma unroll
    for (int r = 0; r < 8; r++) {
        int m = m0 + ty * 8 + r;
        float4 o0, o1;
        o0.x = (accf[r][0] + bv[0] > 0.f) ? 1.f : 0.f;
        o0.y = (accf[r][1] + bv[1] > 0.f) ? 1.f : 0.f;
        o0.z = (accf[r][2] + bv[2] > 0.f) ? 1.f : 0.f;
        o0.w = (accf[r][3] + bv[3] > 0.f) ? 1.f : 0.f;
        o1.x = (accf[r][4] + bv[4] > 0.f) ? 1.f : 0.f;
        o1.y = (accf[r][5] + bv[5] > 0.f) ? 1.f : 0.f;
        o1.z = (accf[r][6] + bv[6] > 0.f) ? 1.f : 0.f;
        o1.w = (accf[r][7] + bv[7] > 0.f) ? 1.f : 0.f;
        *reinterpret_cast<float4*>(&g_S[(size_t)m * EDIM + n0 + tx * 8 + 0]) = o0;
        *reinterpret_cast<float4*>(&g_S[(size_t)m * EDIM + n0 + tx * 8 + 4]) = o1;
    }
}

// ---------------------------------------------------------------------------
// Kernel 2 (FUSED): per (d-slice, b): compute T-tile [256e x 64d] in regs,
// then contract with lm_w in the epilogue and atomicAdd 10 values into out.
// grid (12, 64), 128 thr.
// ---------------------------------------------------------------------------
__global__ __launch_bounds__(128) void k2_fused(
    const float* __restrict__ X, const float* __restrict__ LW,
    float* __restrict__ out)
{
    __shared__ float Ss[2][16][260];
    __shared__ float Xs2[2][16][68];

    const int tid = threadIdx.x;
    const int tx  = tid & 7;     // d dir: 8 each
    const int ty  = tid >> 3;    // e dir: 16 each
    const int b   = blockIdx.y;
    const int d0  = blockIdx.x * 64;

    const float* Sb = &g_S[(size_t)b * HWDIM * EDIM];
    const float* Xb = &X[(size_t)b * HWDIM * DDIM];

    auto issue = [&](int k0, int nb) {
        #pragma unroll
        for (int l = 0; l < 8; l++) {
            int s  = tid + l * 128;
            int h  = s >> 6;
            int e4 = (s & 63) * 4;
            int hh = k0 + h;
            if (hh < HWDIM)
                cp16(&Ss[nb][h][e4], &Sb[(size_t)hh * EDIM + e4]);
            else
                *reinterpret_cast<float4*>(&Ss[nb][h][e4]) =
                    make_float4(0.f, 0.f, 0.f, 0.f);
        }
        #pragma unroll
        for (int l = 0; l < 2; l++) {
            int s  = tid + l * 128;
            int h  = s >> 4;
            int d4 = (s & 15) * 4;
            int hh = k0 + h;
            if (hh < HWDIM)
                cp16(&Xs2[nb][h][d4], &Xb[(size_t)hh * DDIM + d0 + d4]);
            else
                *reinterpret_cast<float4*>(&Xs2[nb][h][d4]) =
                    make_float4(0.f, 0.f, 0.f, 0.f);
        }
        CP_COMMIT();
    };

    issue(0, 0);

    ull acc2[8][8];
    #pragma unroll
    for (int i = 0; i < 8; i++)
        #pragma unroll
        for (int j = 0; j < 8; j++) acc2[i][j] = 0ull;

    int buf = 0;
    const int NT = (HWDIM + 15) / 16;   // 13
    for (int t = 0; t < NT; t++) {
        CP_WAIT0();
        __syncthreads();
        if (t < NT - 1) issue((t + 1) * 16, buf ^ 1);

        #pragma unroll
        for (int kk = 0; kk < 16; kk++) {
            ull ra2[8];
            #pragma unroll
            for (int u = 0; u < 4; u++) {
                ulonglong2 a = *reinterpret_cast<const ulonglong2*>(
                    &Ss[buf][kk][ty * 16 + u * 4]);
                ra2[2 * u + 0] = a.x;
                ra2[2 * u + 1] = a.y;
            }
            float rbv[8];
            *reinterpret_cast<float4*>(&rbv[0]) =
                *reinterpret_cast<const float4*>(&Xs2[buf][kk][tx * 8 + 0]);
            *reinterpret_cast<float4*>(&rbv[4]) =
                *reinterpret_cast<const float4*>(&Xs2[buf][kk][tx * 8 + 4]);
            ull rb2[8];
            #pragma unroll
            for (int j = 0; j < 8; j++) PACK2(rb2[j], rbv[j]);
            #pragma unroll
            for (int i = 0; i < 8; i++)
                #pragma unroll
                for (int j = 0; j < 8; j++) FMA2(acc2[i][j], ra2[i], rb2[j]);
        }
        buf ^= 1;
    }

    // ---- fused epilogue: partial[c] += T[e][d] * LW[e*CDIM+c][d]
    float partial[CDIM];
    #pragma unroll
    for (int c = 0; c < CDIM; c++) partial[c] = 0.f;

    #pragma unroll
    for (int i = 0; i < 8; i++) {
        float elo[8], ehi[8];
        #pragma unroll
        for (int j = 0; j < 8; j++) UNPACK2(elo[j], ehi[j], acc2[i][j]);
        const int e0 = ty * 16 + 2 * i;
        #pragma unroll
        for (int c = 0; c < CDIM; c++) {
            const float* r0 = &LW[((size_t)e0 * CDIM + c) * DDIM + d0 + tx * 8];
            const float* r1 = &LW[((size_t)(e0 + 1) * CDIM + c) * DDIM + d0 + tx * 8];
            float4 a0 = *reinterpret_cast<const float4*>(r0 + 0);
            float4 a1 = *reinterpret_cast<const float4*>(r0 + 4);
            float4 b0 = *reinterpret_cast<const float4*>(r1 + 0);
            float4 b1 = *reinterpret_cast<const float4*>(r1 + 4);
            float s = 0.f;
            s += elo[0] * a0.x + elo[1] * a0.y + elo[2] * a0.z + elo[3] * a0.w;
            s += elo[4] * a1.x + elo[5] * a1.y + elo[6] * a1.z + elo[7] * a1.w;
            s += ehi[0] * b0.x + ehi[1] * b0.y + ehi[2] * b0.z + ehi[3] * b0.w;
            s += ehi[4] * b1.x + ehi[5] * b1.y + ehi[6] * b1.z + ehi[7] * b1.w;
            partial[c] += s;
        }
    }

    // ---- block reduction over 128 threads (reuse Ss as scratch)
    float* red = &Ss[0][0][0];
    __syncthreads();
    #pragma unroll
    for (int c = 0; c < CDIM; c++) red[c * 128 + tid] = partial[c];
    __syncthreads();

    #pragma unroll
    for (int off = 64; off >= 1; off >>= 1) {
        if (tid < off) {
            #pragma unroll
            for (int c = 0; c < CDIM; c++)
                red[c * 128 + tid] += red[c * 128 + tid + off];
        }
        __syncthreads();
    }

    const float scale = 1.0f / ((float)HWDIM * (float)EDIM);
    if (tid < CDIM)
        atomicAdd(&out[b * CDIM + tid], red[tid * 128] * scale);
}

// ---------------------------------------------------------------------------
// Zero the output (harness poisons it; atomics accumulate into it).
// ---------------------------------------------------------------------------
__global__ void k_zero(float* __restrict__ out)
{
    int p = blockIdx.x * blockDim.x + threadIdx.x;
    if (p < BATCH * CDIM) out[p] = 0.f;
}

// ---------------------------------------------------------------------------
extern "C" void kernel_launch(void* const* d_in, const int* in_sizes, int n_in,
                              void* d_out, int out_size)
{
    const float* X   = (const float*)d_in[0];   // (64,196,768)
    const float* AGW = (const float*)d_in[1];   // (256,768)
    const float* AGB = (const float*)d_in[2];   // (256,)
    const float* LW  = (const float*)d_in[3];   // (2560,768)
    float* out = (float*)d_out;                 // (64,10)

    k1_sign_gemm<<<dim3(EDIM / 64, M1 / 128), 128>>>(X, AGW, AGB);
    k_zero<<<3, 256>>>(out);
    k2_fused<<<dim3(DDIM / 64, BATCH), 128>>>(X, LW, out);
}

// round 10
// speedup vs baseline: 1.0667x; 1.0667x over previous
#include <cuda_runtime.h>
#include <cuda_bf16.h>
#include <cstdint>

// Problem dims (fixed by reference)
#define HWDIM 196
#define BATCH 64
#define DDIM  768
#define EDIM  256
#define CDIM  10
#define M1    (BATCH * HWDIM)   // 12544 rows (b,h)

typedef unsigned long long ull;

// ---------------- f32x2 helpers (k2_fused) ----------------
#define FMA2(acc, a, b) \
    asm("fma.rn.f32x2 %0, %1, %2, %0;" : "+l"(acc) : "l"(a), "l"(b))
#define PACK2(p, v) \
    asm("mov.b64 %0, {%1, %1};" : "=l"(p) : "f"(v))
#define UNPACK2(lo, hi, p) \
    asm("mov.b64 {%0, %1}, %2;" : "=f"(lo), "=f"(hi) : "l"(p))

__device__ __forceinline__ void cp16(void* smem_dst, const void* gsrc) {
    unsigned sa = (unsigned)__cvta_generic_to_shared(smem_dst);
    asm volatile("cp.async.cg.shared.global [%0], [%1], 16;" :: "r"(sa), "l"(gsrc));
}
__device__ __forceinline__ void cp16s(uint32_t smem_dst, const void* gsrc) {
    asm volatile("cp.async.cg.shared.global [%0], [%1], 16;" :: "r"(smem_dst), "l"(gsrc));
}
#define CP_COMMIT() asm volatile("cp.async.commit_group;")
#define CP_WAIT0()  asm volatile("cp.async.wait_group 0;")

__device__ __forceinline__ uint32_t smem_u32(const void* p) {
    uint32_t a;
    asm("{ .reg .u64 t; cvta.to.shared.u64 t, %1; cvt.u32.u64 %0, t; }"
        : "=r"(a) : "l"(p));
    return a;
}

// ---------------- warp-level bf16 MMA (sm_80+ PTX, no 'a' features) --------
#define LDSM_X4(r0, r1, r2, r3, addr) \
    asm volatile("ldmatrix.sync.aligned.m8n8.x4.shared.b16 {%0,%1,%2,%3}, [%4];" \
                 : "=r"(r0), "=r"(r1), "=r"(r2), "=r"(r3) : "r"(addr))

#define MMA16816(d, a0, a1, a2, a3, b0, b1) \
    asm volatile("mma.sync.aligned.m16n8k16.row.col.f32.bf16.bf16.f32 " \
                 "{%0,%1,%2,%3}, {%4,%5,%6,%7}, {%8,%9}, {%0,%1,%2,%3};" \
                 : "+f"((d)[0]), "+f"((d)[1]), "+f"((d)[2]), "+f"((d)[3]) \
                 : "r"(a0), "r"(a1), "r"(a2), "r"(a3), "r"(b0), "r"(b1))

// ---------------- scratch (static device globals) ----------------
__device__ float          g_S[(size_t)M1 * EDIM];        // sign pattern, 12.8 MB
__device__ __nv_bfloat16  g_Xhi[(size_t)M1 * DDIM];      // 19.3 MB
__device__ __nv_bfloat16  g_Xlo[(size_t)M1 * DDIM];      // 19.3 MB
__device__ __nv_bfloat16  g_Whi[(size_t)EDIM * DDIM];
__device__ __nv_bfloat16  g_Wlo[(size_t)EDIM * DDIM];

// ---------------------------------------------------------------------------
// k0: split fp32 -> bf16 hi + bf16 lo (residual).
// ---------------------------------------------------------------------------
__global__ void k0_split_x(const float* __restrict__ X)
{
    int i = blockIdx.x * 256 + threadIdx.x;   // float4 index, grid exact
    float4 v = reinterpret_cast<const float4*>(X)[i];
    __nv_bfloat162 h01 = __floats2bfloat162_rn(v.x, v.y);
    __nv_bfloat162 h23 = __floats2bfloat162_rn(v.z, v.w);
    float r0 = v.x - __bfloat162float(h01.x);
    float r1 = v.y - __bfloat162float(h01.y);
    float r2 = v.z - __bfloat162float(h23.x);
    float r3 = v.w - __bfloat162float(h23.y);
    __nv_bfloat162 l01 = __floats2bfloat162_rn(r0, r1);
    __nv_bfloat162 l23 = __floats2bfloat162_rn(r2, r3);
    reinterpret_cast<__nv_bfloat162*>(g_Xhi)[2 * i + 0] = h01;
    reinterpret_cast<__nv_bfloat162*>(g_Xhi)[2 * i + 1] = h23;
    reinterpret_cast<__nv_bfloat162*>(g_Xlo)[2 * i + 0] = l01;
    reinterpret_cast<__nv_bfloat162*>(g_Xlo)[2 * i + 1] = l23;
}

__global__ void k0_split_w(const float* __restrict__ W)
{
    int i = blockIdx.x * 256 + threadIdx.x;
    float4 v = reinterpret_cast<const float4*>(W)[i];
    __nv_bfloat162 h01 = __floats2bfloat162_rn(v.x, v.y);
    __nv_bfloat162 h23 = __floats2bfloat162_rn(v.z, v.w);
    float r0 = v.x - __bfloat162float(h01.x);
    float r1 = v.y - __bfloat162float(h01.y);
    float r2 = v.z - __bfloat162float(h23.x);
    float r3 = v.w - __bfloat162float(h23.y);
    __nv_bfloat162 l01 = __floats2bfloat162_rn(r0, r1);
    __nv_bfloat162 l23 = __floats2bfloat162_rn(r2, r3);
    reinterpret_cast<__nv_bfloat162*>(g_Whi)[2 * i + 0] = h01;
    reinterpret_cast<__nv_bfloat162*>(g_Whi)[2 * i + 1] = h23;
    reinterpret_cast<__nv_bfloat162*>(g_Wlo)[2 * i + 0] = l01;
    reinterpret_cast<__nv_bfloat162*>(g_Wlo)[2 * i + 1] = l23;
}

// ---------------------------------------------------------------------------
// Kernel 1 (HMMA): S = sign(X @ W^T + b) via bf16 3-product split GEMM on
// mma.sync m16n8k16. Block 128(M)x64(N), 4 warps (each 32Mx64N), K-concat
// 36 chunks of K=64 over [Xhi*Whi | Xhi*Wlo | Xlo*Whi]. cp.async dbl-buffer.
// Borderline |z| < 0.05 refined with exact fp32 dot -> signs fp32-exact.
// grid (4, 98), 128 threads, dyn smem 55296 B.
// ---------------------------------------------------------------------------
#define K1_SMEM 55296
#define APITCH  144               // 72 bf16 per row (64 data + 8 pad)
#define A_OFF(buf) ((buf) * 18432)
#define B_OFF(buf) (36864 + (buf) * 9216)

__global__ __launch_bounds__(128) void k1_mma(
    const float* __restrict__ X, const float* __restrict__ W,
    const float* __restrict__ bias)
{
    extern __shared__ char smem[];
    const uint32_t sbase = smem_u32(smem);
    const int tid  = threadIdx.x;
    const int w    = tid >> 5;
    const int lane = tid & 31;
    const int m0   = blockIdx.y * 128;
    const int n0   = blockIdx.x * 64;

    const __nv_bfloat16* Aseg[3] = { g_Xhi, g_Xhi, g_Xlo };
    const __nv_bfloat16* Bseg[3] = { g_Whi, g_Wlo, g_Whi };

    // stage a K64 chunk: A 128x64 bf16 (8 chunks/thread), B 64x64 (4/thread)
    auto issue = [&](int t, int buf) {
        const int seg = t / 12;
        const int kk0 = (t % 12) * 64;
        const __nv_bfloat16* Ab = Aseg[seg];
        const __nv_bfloat16* Bb = Bseg[seg];
        const uint32_t a_s = sbase + A_OFF(buf);
        const uint32_t b_s = sbase + B_OFF(buf);
        #pragma unroll
        for (int l = 0; l < 8; l++) {
            int s = tid + l * 128;
            int r = s >> 3, c = s & 7;
            cp16s(a_s + r * APITCH + c * 16,
                  Ab + (size_t)(m0 + r) * DDIM + kk0 + c * 8);
        }
        #pragma unroll
        for (int l = 0; l < 4; l++) {
            int s = tid + l * 128;
            int r = s >> 3, c = s & 7;
            cp16s(b_s + r * APITCH + c * 16,
                  Bb + (size_t)(n0 + r) * DDIM + kk0 + c * 8);
        }
        CP_COMMIT();
    };

    issue(0, 0);

    float acc[2][8][4];
    #pragma unroll
    for (int i = 0; i < 2; i++)
        #pragma unroll
        for (int j = 0; j < 8; j++)
            #pragma unroll
            for (int c = 0; c < 4; c++) acc[i][j][c] = 0.f;

    const int lrow = lane & 15;          // ldmatrix row within 16
    const int lcol = (lane >> 4) * 16;   // 0 or 16 bytes (k 0-7 / 8-15)

    for (int t = 0; t < 36; t++) {
        CP_WAIT0();
        __syncthreads();
        if (t < 35) issue(t + 1, (t + 1) & 1);

        const uint32_t a_s = sbase + A_OFF(t & 1);
        const uint32_t b_s = sbase + B_OFF(t & 1);

        #pragma unroll
        for (int kk = 0; kk < 4; kk++) {
            const uint32_t kb = kk * 32;
            uint32_t ra[2][4], rb[4][4];
            #pragma unroll
            for (int i = 0; i < 2; i++) {
                uint32_t ad = a_s + (w * 32 + i * 16 + lrow) * APITCH + kb + lcol;
                LDSM_X4(ra[i][0], ra[i][1], ra[i][2], ra[i][3], ad);
            }
            #pragma unroll
            for (int j2 = 0; j2 < 4; j2++) {
                uint32_t bd = b_s + (j2 * 16 + lrow) * APITCH + kb + lcol;
                LDSM_X4(rb[j2][0], rb[j2][1], rb[j2][2], rb[j2][3], bd);
            }
            #pragma unroll
            for (int i = 0; i < 2; i++)
                #pragma unroll
                for (int j2 = 0; j2 < 4; j2++) {
                    MMA16816(acc[i][2 * j2 + 0],
                             ra[i][0], ra[i][1], ra[i][2], ra[i][3],
                             rb[j2][0], rb[j2][2]);
                    MMA16816(acc[i][2 * j2 + 1],
                             ra[i][0], ra[i][1], ra[i][2], ra[i][3],
                             rb[j2][1], rb[j2][3]);
                }
        }
    }

    // ---- epilogue: bias + sign + borderline mask -------------------------
    // acc[i][j][c] is z at m = m0 + w*32 + i*16 + (lane>>2) + 8*(c>>1),
    //                   n = n0 + j*8  + (lane&3)*2 + (c&1)
    const int mrow = lane >> 2;
    const int ncol = (lane & 3) * 2;
    ull border = 0ull;

    #pragma unroll
    for (int i = 0; i < 2; i++) {
        #pragma unroll
        for (int j = 0; j < 8; j++) {
            const int n = n0 + j * 8 + ncol;
            const float b0 = __ldg(&bias[n]);
            const float b1 = __ldg(&bias[n + 1]);
            float v0 = acc[i][j][0] + b0;
            float v1 = acc[i][j][1] + b1;
            float v2 = acc[i][j][2] + b0;
            float v3 = acc[i][j][3] + b1;
            if (fabsf(v0) < 0.05f) border |= 1ull << (i * 32 + j * 4 + 0);
            if (fabsf(v1) < 0.05f) border |= 1ull << (i * 32 + j * 4 + 1);
            if (fabsf(v2) < 0.05f) border |= 1ull << (i * 32 + j * 4 + 2);
            if (fabsf(v3) < 0.05f) border |= 1ull << (i * 32 + j * 4 + 3);
            const int mA = m0 + w * 32 + i * 16 + mrow;
            float2 oA = make_float2(v0 > 0.f ? 1.f : 0.f, v1 > 0.f ? 1.f : 0.f);
            float2 oB = make_float2(v2 > 0.f ? 1.f : 0.f, v3 > 0.f ? 1.f : 0.f);
            *reinterpret_cast<float2*>(&g_S[(size_t)mA * EDIM + n]) = oA;
            *reinterpret_cast<float2*>(&g_S[(size_t)(mA + 8) * EDIM + n]) = oB;
        }
    }

    // ---- exact fp32 refinement of borderline signs (~0.14% of entries) ---
    while (border) {
        int q = __ffsll(border) - 1;
        border &= border - 1;
        int i = q >> 5, j = (q >> 2) & 7, c = q & 3;
        int m = m0 + w * 32 + i * 16 + mrow + 8 * (c >> 1);
        int n = n0 + j * 8 + ncol + (c & 1);
        const float* xrow = X + (size_t)m * DDIM;
        const float* wrow = W + (size_t)n * DDIM;
        float s = 0.f;
        #pragma unroll 4
        for (int d = 0; d < DDIM / 4; d++) {
            float4 xv = reinterpret_cast<const float4*>(xrow)[d];
            float4 wv = reinterpret_cast<const float4*>(wrow)[d];
            s += xv.x * wv.x + xv.y * wv.y + xv.z * wv.z + xv.w * wv.w;
        }
        float v = s + __ldg(&bias[n]);
        g_S[(size_t)m * EDIM + n] = (v > 0.f) ? 1.f : 0.f;
    }
}

// ---------------------------------------------------------------------------
// Kernel 2 (FUSED, unchanged R7 winner): per (d-slice, b) compute T-tile
// [256e x 64d] in regs, contract with lm_w, atomicAdd into out.
// ---------------------------------------------------------------------------
__global__ __launch_bounds__(128) void k2_fused(
    const float* __restrict__ X, const float* __restrict__ LW,
    float* __restrict__ out)
{
    __shared__ float Ss[2][16][260];
    __shared__ float Xs2[2][16][68];

    const int tid = threadIdx.x;
    const int tx  = tid & 7;
    const int ty  = tid >> 3;
    const int b   = blockIdx.y;
    const int d0  = blockIdx.x * 64;

    const float* Sb = &g_S[(size_t)b * HWDIM * EDIM];
    const float* Xb = &X[(size_t)b * HWDIM * DDIM];

    auto issue = [&](int k0, int nb) {
        #pragma unroll
        for (int l = 0; l < 8; l++) {
            int s  = tid + l * 128;
            int h  = s >> 6;
            int e4 = (s & 63) * 4;
            int hh = k0 + h;
            if (hh < HWDIM)
                cp16(&Ss[nb][h][e4], &Sb[(size_t)hh * EDIM + e4]);
            else
                *reinterpret_cast<float4*>(&Ss[nb][h][e4]) =
                    make_float4(0.f, 0.f, 0.f, 0.f);
        }
        #pragma unroll
        for (int l = 0; l < 2; l++) {
            int s  = tid + l * 128;
            int h  = s >> 4;
            int d4 = (s & 15) * 4;
            int hh = k0 + h;
            if (hh < HWDIM)
                cp16(&Xs2[nb][h][d4], &Xb[(size_t)hh * DDIM + d0 + d4]);
            else
                *reinterpret_cast<float4*>(&Xs2[nb][h][d4]) =
                    make_float4(0.f, 0.f, 0.f, 0.f);
        }
        CP_COMMIT();
    };

    issue(0, 0);

    ull acc2[8][8];
    #pragma unroll
    for (int i = 0; i < 8; i++)
        #pragma unroll
        for (int j = 0; j < 8; j++) acc2[i][j] = 0ull;

    int buf = 0;
    const int NT = (HWDIM + 15) / 16;   // 13
    for (int t = 0; t < NT; t++) {
        CP_WAIT0();
        __syncthreads();
        if (t < NT - 1) issue((t + 1) * 16, buf ^ 1);

        #pragma unroll
        for (int kk = 0; kk < 16; kk++) {
            ull ra2[8];
            #pragma unroll
            for (int u = 0; u < 4; u++) {
                ulonglong2 a = *reinterpret_cast<const ulonglong2*>(
                    &Ss[buf][kk][ty * 16 + u * 4]);
                ra2[2 * u + 0] = a.x;
                ra2[2 * u + 1] = a.y;
            }
            float rbv[8];
            *reinterpret_cast<float4*>(&rbv[0]) =
                *reinterpret_cast<const float4*>(&Xs2[buf][kk][tx * 8 + 0]);
            *reinterpret_cast<float4*>(&rbv[4]) =
                *reinterpret_cast<const float4*>(&Xs2[buf][kk][tx * 8 + 4]);
            ull rb2[8];
            #pragma unroll
            for (int j = 0; j < 8; j++) PACK2(rb2[j], rbv[j]);
            #pragma unroll
            for (int i = 0; i < 8; i++)
                #pragma unroll
                for (int j = 0; j < 8; j++) FMA2(acc2[i][j], ra2[i], rb2[j]);
        }
        buf ^= 1;
    }

    float partial[CDIM];
    #pragma unroll
    for (int c = 0; c < CDIM; c++) partial[c] = 0.f;

    #pragma unroll
    for (int i = 0; i < 8; i++) {
        float elo[8], ehi[8];
        #pragma unroll
        for (int j = 0; j < 8; j++) UNPACK2(elo[j], ehi[j], acc2[i][j]);
        const int e0 = ty * 16 + 2 * i;
        #pragma unroll
        for (int c = 0; c < CDIM; c++) {
            const float* r0 = &LW[((size_t)e0 * CDIM + c) * DDIM + d0 + tx * 8];
            const float* r1 = &LW[((size_t)(e0 + 1) * CDIM + c) * DDIM + d0 + tx * 8];
            float4 a0 = *reinterpret_cast<const float4*>(r0 + 0);
            float4 a1 = *reinterpret_cast<const float4*>(r0 + 4);
            float4 b0 = *reinterpret_cast<const float4*>(r1 + 0);
            float4 b1 = *reinterpret_cast<const float4*>(r1 + 4);
            float s = 0.f;
            s += elo[0] * a0.x + elo[1] * a0.y + elo[2] * a0.z + elo[3] * a0.w;
            s += elo[4] * a1.x + elo[5] * a1.y + elo[6] * a1.z + elo[7] * a1.w;
            s += ehi[0] * b0.x + ehi[1] * b0.y + ehi[2] * b0.z + ehi[3] * b0.w;
            s += ehi[4] * b1.x + ehi[5] * b1.y + ehi[6] * b1.z + ehi[7] * b1.w;
            partial[c] += s;
        }
    }

    float* red = &Ss[0][0][0];
    __syncthreads();
    #pragma unroll
    for (int c = 0; c < CDIM; c++) red[c * 128 + tid] = partial[c];
    __syncthreads();

    #pragma unroll
    for (int off = 64; off >= 1; off >>= 1) {
        if (tid < off) {
            #pragma unroll
            for (int c = 0; c < CDIM; c++)
                red[c * 128 + tid] += red[c * 128 + tid + off];
        }
        __syncthreads();
    }

    const float scale = 1.0f / ((float)HWDIM * (float)EDIM);
    if (tid < CDIM)
        atomicAdd(&out[b * CDIM + tid], red[tid * 128] * scale);
}

// ---------------------------------------------------------------------------
__global__ void k_zero(float* __restrict__ out)
{
    int p = blockIdx.x * blockDim.x + threadIdx.x;
    if (p < BATCH * CDIM) out[p] = 0.f;
}

// ---------------------------------------------------------------------------
extern "C" void kernel_launch(void* const* d_in, const int* in_sizes, int n_in,
                              void* d_out, int out_size)
{
    const float* X   = (const float*)d_in[0];   // (64,196,768)
    const float* AGW = (const float*)d_in[1];   // (256,768)
    const float* AGB = (const float*)d_in[2];   // (256,)
    const float* LW  = (const float*)d_in[3];   // (2560,768)
    float* out = (float*)d_out;                 // (64,10)

    cudaFuncSetAttribute(k1_mma, cudaFuncAttributeMaxDynamicSharedMemorySize,
                         K1_SMEM);

    k0_split_x<<<(M1 * DDIM / 4) / 256, 256>>>(X);          // 9408 blocks
    k0_split_w<<<(EDIM * DDIM / 4) / 256, 256>>>(AGW);      // 192 blocks
    k_zero<<<3, 256>>>(out);
    k1_mma<<<dim3(EDIM / 64, M1 / 128), 128, K1_SMEM>>>(X, AGW, AGB);
    k2_fused<<<dim3(DDIM / 64, BATCH), 128>>>(X, LW, out);
}